// round 5
// baseline (speedup 1.0000x reference)
#include <cuda_runtime.h>
#include <math.h>

// ---------------- scratch ----------------
__device__ float g_bufA[800L*64*42*42];   // conv1 out
__device__ float g_bufB[800L*64*21*21];   // conv2 out
__device__ float g_bufC[800L*64*11*11];   // conv3 out
__device__ float g_bufD[800L*2304];       // conv4 out (embeddings)
__device__ float g_protos[8*5*2304];
__device__ float g_protoInv[8*5];
// prepacked weights: [c][cout][ky][4] floats (kx3 = 0 pad)
__device__ float g_wp1[3*64*12];
__device__ float g_wp2[64*64*12];
__device__ float g_wp3[64*64*12];
__device__ float g_wp4[64*64*12];

// ---------------- weight prepack: OIHW -> [c][cout][ky][4] ----------------
__global__ void prepack_kernel(const float* __restrict__ w, float* __restrict__ wp, int CIN)
{
    int gid = blockIdx.x * 256 + threadIdx.x;
    int total = CIN * 64 * 12;
    if (gid >= total) return;
    int c    = gid / (64*12);
    int rem  = gid - c*(64*12);
    int cout = rem / 12;
    int k    = rem - cout*12;
    int ky   = k >> 2, kx = k & 3;
    wp[gid] = (kx < 3) ? w[(cout*CIN + c)*9 + ky*3 + kx] : 0.f;
}

// ---------------- stride-2 3x3 conv + bias + relu --------------------------
// Block: image n, OYT output rows, all 64 couts (8 groups x 8 couts).
// Thread: 8 couts x 4 CONSECUTIVE x positions (one quad).
// Input smem de-interleaved into even/odd column planes:
//   output x needs raw cols 2x,2x+1,2x+2 = even[x], odd[x], even[x+1]
//   -> 4 positions/ky: LDS.128 even[x0..3] + LDS.32 even[x0+4] + LDS.128 odd[x0..3]
template<int CIN, int H, int OH, int PADLOW, int OYT, int XT, int CK>
__global__ void __launch_bounds__(8*OYT*XT)
conv_s2_kernel(const float* __restrict__ in, const float* __restrict__ wp,
               const float* __restrict__ bias, float* __restrict__ out)
{
    constexpr int W = H, OW = OH;
    constexpr int PX   = OYT*XT;          // quads per cout-group
    constexpr int NT   = 8*PX;
    constexpr int RP   = 2*OYT + 1;
    constexpr int EP   = 4*XT + 4;        // plane pitch, mult of 4
    constexpr int ROWF = 2*EP;            // floats per (c,r) row (both planes)
    constexpr int SRAW = 8*XT + 1;        // raw columns staged
    constexpr int IN_SZ = CK*RP*ROWF;
    constexpr int W_SZ  = CK*64*12;       // floats

    __shared__ __align__(16) float s_in[IN_SZ];
    __shared__ __align__(16) float s_w[W_SZ];

    const int n   = blockIdx.x;
    const int oy0 = blockIdx.y * OYT;
    const int tid = threadIdx.x;
    const int cy  = tid / PX;             // cout group 0..7 -> couts cy*8..cy*8+7
    const int px  = tid % PX;
    const int oyl = px / XT;
    const int x0  = (px % XT) * 4;

    float acc[8][4];
#pragma unroll
    for (int i = 0; i < 8; i++)
#pragma unroll
        for (int j = 0; j < 4; j++) acc[i][j] = 0.f;

    for (int c0 = 0; c0 < CIN; c0 += CK) {
        // ---- stage input tile, de-interleaved even/odd columns ----
        for (int idx = tid; idx < CK*RP*SRAW; idx += NT) {
            int c   = idx / (RP*SRAW);
            int rem = idx - c*(RP*SRAW);
            int r   = rem / SRAW;
            int s   = rem - r*SRAW;
            int gr  = 2*oy0 + r - PADLOW;
            int gc  = s - PADLOW;
            float v = 0.f;
            if (gr >= 0 && gr < H && gc >= 0 && gc < W)
                v = in[((n*CIN + c0 + c)*H + gr)*W + gc];
            s_in[(c*RP + r)*ROWF + (s & 1)*EP + (s >> 1)] = v;
        }
        // ---- stage prepacked weights: straight float4 copy ----
        {
            const float4* src = (const float4*)(wp + c0*(64*12));
            float4* dst = (float4*)s_w;
            for (int idx = tid; idx < W_SZ/4; idx += NT)
                dst[idx] = src[idx];
        }
        __syncthreads();

#pragma unroll
        for (int c = 0; c < CK; c++) {
            const float* base = &s_in[(c*RP + 2*oyl)*ROWF + x0];
#pragma unroll
            for (int ky = 0; ky < 3; ky++) {
                const float* rp = base + ky*ROWF;
                float4 E = *(const float4*)rp;        // even[x0..x0+3]
                float  e4 = rp[4];                     // even[x0+4]
                float4 O = *(const float4*)(rp + EP);  // odd [x0..x0+3]
                const float Ev[5] = {E.x, E.y, E.z, E.w, e4};
                const float Ov[4] = {O.x, O.y, O.z, O.w};
#pragma unroll
                for (int co = 0; co < 8; co++) {
                    float4 wv = *(const float4*)&s_w[((c*64 + cy*8 + co)*3 + ky)*4];
#pragma unroll
                    for (int p = 0; p < 4; p++) {
                        float a = acc[co][p];
                        a = fmaf(wv.x, Ev[p],   a);
                        a = fmaf(wv.y, Ov[p],   a);
                        a = fmaf(wv.z, Ev[p+1], a);
                        acc[co][p] = a;
                    }
                }
            }
        }
        __syncthreads();
    }

    // ---- epilogue ----
    const int oy = oy0 + oyl;
    if (oy < OH) {
#pragma unroll
        for (int co = 0; co < 8; co++) {
            const int cout = cy*8 + co;
            const float bb = bias[cout];
            float* op = &out[((n*64 + cout)*OH + oy)*OW];
#pragma unroll
            for (int p = 0; p < 4; p++) {
                int x = x0 + p;
                if (x < OW) {
                    float v = acc[co][p] + bb;
                    op[x] = v > 0.f ? v : 0.f;
                }
            }
        }
    }
}

// ---------------- prototypes + inverse norms ----------------
__global__ void protos_kernel(const float* __restrict__ emb, const int* __restrict__ y,
                              float* __restrict__ protos, float* __restrict__ protoInv)
{
    const int b = blockIdx.x / 5, c = blockIdx.x % 5;
    const int tid = threadIdx.x;                   // 256
    __shared__ int sels[25];
    if (tid < 25) sels[tid] = ((y[b*25 + tid] % 5) == c) ? 1 : 0;
    __syncthreads();

    float sq = 0.f;
    for (int d = tid; d < 2304; d += 256) {
        float v = 0.f;
#pragma unroll
        for (int s = 0; s < 25; s++)
            if (sels[s]) v += emb[(b*25 + s)*2304 + d];
        v = v / 5.0f;                              // CAP = 5
        protos[(b*5 + c)*2304 + d] = v;
        sq += v*v;
    }
    __shared__ float red[256];
    red[tid] = sq; __syncthreads();
    for (int s = 128; s > 0; s >>= 1) {
        if (tid < s) red[tid] += red[tid + s];
        __syncthreads();
    }
    if (tid == 0) protoInv[b*5 + c] = 1.f / fmaxf(sqrtf(red[0]), 1e-8f);
}

// ---------------- cosine logits ----------------
__global__ void preds_kernel(const float* __restrict__ emb, const float* __restrict__ protos,
                             const float* __restrict__ protoInv, float* __restrict__ out)
{
    const int b = blockIdx.x / 75, t = blockIdx.x % 75;
    const int tid = threadIdx.x;                   // 256
    float dot[5] = {0,0,0,0,0};
    float nsq = 0.f;
    const float* e = emb + (size_t)(200 + b*75 + t)*2304;
    for (int d = tid; d < 2304; d += 256) {
        float ev = e[d];
        nsq += ev*ev;
#pragma unroll
        for (int c = 0; c < 5; c++)
            dot[c] = fmaf(ev, protos[(b*5 + c)*2304 + d], dot[c]);
    }
    __shared__ float red[256];
    __shared__ float res[6];
    for (int q = 0; q < 6; q++) {
        red[tid] = (q == 0) ? nsq : dot[q-1];
        __syncthreads();
        for (int s = 128; s > 0; s >>= 1) {
            if (tid < s) red[tid] += red[tid + s];
            __syncthreads();
        }
        if (tid == 0) res[q] = red[0];
        __syncthreads();
    }
    if (tid < 5) {
        float inv_t = 1.f / fmaxf(sqrtf(res[0]), 1e-8f);
        out[(b*75 + t)*5 + tid] = res[1 + tid] * inv_t * protoInv[b*5 + tid];
    }
}

// ---------------- launch ----------------
extern "C" void kernel_launch(void* const* d_in, const int* in_sizes, int n_in,
                              void* d_out, int out_size)
{
    const float* xs = (const float*)d_in[0];
    const float* xt = (const float*)d_in[1];
    const int*   y  = (const int*)  d_in[2];
    const float* W1 = (const float*)d_in[3];
    const float* b1 = (const float*)d_in[4];
    const float* W2 = (const float*)d_in[5];
    const float* b2 = (const float*)d_in[6];
    const float* W3 = (const float*)d_in[7];
    const float* b3 = (const float*)d_in[8];
    const float* W4 = (const float*)d_in[9];
    const float* b4 = (const float*)d_in[10];
    float* out = (float*)d_out;

    float *bufA, *bufB, *bufC, *bufD, *pr, *pi;
    float *wp1, *wp2, *wp3, *wp4;
    cudaGetSymbolAddress((void**)&bufA, g_bufA);
    cudaGetSymbolAddress((void**)&bufB, g_bufB);
    cudaGetSymbolAddress((void**)&bufC, g_bufC);
    cudaGetSymbolAddress((void**)&bufD, g_bufD);
    cudaGetSymbolAddress((void**)&pr,   g_protos);
    cudaGetSymbolAddress((void**)&pi,   g_protoInv);
    cudaGetSymbolAddress((void**)&wp1,  g_wp1);
    cudaGetSymbolAddress((void**)&wp2,  g_wp2);
    cudaGetSymbolAddress((void**)&wp3,  g_wp3);
    cudaGetSymbolAddress((void**)&wp4,  g_wp4);

    // prepack weights (tiny)
    prepack_kernel<<<(3*64*12 + 255)/256, 256>>>(W1, wp1, 3);
    prepack_kernel<<<(64*64*12 + 255)/256, 256>>>(W2, wp2, 64);
    prepack_kernel<<<(64*64*12 + 255)/256, 256>>>(W3, wp3, 64);
    prepack_kernel<<<(64*64*12 + 255)/256, 256>>>(W4, wp4, 64);

    // <CIN,H,OH,PADLOW, OYT,XT,CK>
    // conv1: 3->64, 84->42. OYT=4, XT=11 (44 cols), NT=352, grid(.,11)
    conv_s2_kernel<3,84,42,0, 4,11,3><<<dim3(200,11), 352>>>(xs, wp1, b1, bufA);
    conv_s2_kernel<3,84,42,0, 4,11,3><<<dim3(600,11), 352>>>(xt, wp1, b1, bufA + (size_t)200*64*42*42);
    // conv2: 64->64, 42->21. OYT=7, XT=6 (24 cols), NT=336, grid(800,3)
    conv_s2_kernel<64,42,21,0, 7,6,8><<<dim3(800,3), 336>>>(bufA, wp2, b2, bufB);
    // conv3: 64->64, 21->11, pad_low=1. OYT=11 (whole), XT=3, NT=264, grid(800,1)
    conv_s2_kernel<64,21,11,1, 11,3,8><<<dim3(800,1), 264>>>(bufB, wp3, b3, bufC);
    // conv4: 64->64, 11->6, pad_low=1. OYT=6 (whole), XT=2, NT=96, grid(800,1)
    conv_s2_kernel<64,11,6,1, 6,2,8><<<dim3(800,1), 96>>>(bufC, wp4, b4, bufD);
    // head
    protos_kernel<<<40, 256>>>(bufD, y, pr, pi);
    preds_kernel<<<600, 256>>>(bufD, pr, pi, out);
}

// round 6
// speedup vs baseline: 1.0702x; 1.0702x over previous
#include <cuda_runtime.h>
#include <math.h>

// ---------------- scratch ----------------
__device__ float g_bufA[800L*64*42*42];   // conv1 out
__device__ float g_bufB[800L*64*21*21];   // conv2 out
__device__ float g_bufC[800L*64*11*11];   // conv3 out
__device__ float g_bufD[800L*2304];       // conv4 out (embeddings)
__device__ float g_protos[8*5*2304];
__device__ float g_protoInv[8*5];
// prepacked weights: [c][cout][ky][4] floats (kx3 = 0 pad)
__device__ float g_wp1[3*64*12];
__device__ float g_wp2[64*64*12];
__device__ float g_wp3[64*64*12];
__device__ float g_wp4[64*64*12];

// ---------------- weight prepack: OIHW -> [c][cout][ky][4] ----------------
__global__ void prepack_kernel(const float* __restrict__ w, float* __restrict__ wp, int CIN)
{
    int gid = blockIdx.x * 256 + threadIdx.x;
    int total = CIN * 64 * 12;
    if (gid >= total) return;
    int c    = gid / (64*12);
    int rem  = gid - c*(64*12);
    int cout = rem / 12;
    int k    = rem - cout*12;
    int ky   = k >> 2, kx = k & 3;
    wp[gid] = (kx < 3) ? w[(cout*CIN + c)*9 + ky*3 + kx] : 0.f;
}

// ---------------- stride-2 3x3 conv + bias + relu --------------------------
// Block: image n, OYT output rows, all 64 couts (8 groups x 8 couts).
// Thread: 8 couts x 4 CONSECUTIVE x positions (one quad).
// Input smem de-interleaved into even/odd column planes:
//   output x needs raw cols 2x,2x+1,2x+2 = even[x], odd[x], even[x+1]
//   -> per ky: LDS.128 even[x0..3] + LDS.32 even[x0+4] + LDS.128 odd[x0..3]
// ROWF = 2*EP + 4 keeps the row pitch off 32-word multiples so different
// oyl rows in a warp hit different bank groups (R5's pitch was ROWF=2*EP,
// a multiple of 32 for conv1/conv3 -> up to 11-way conflicts).
template<int CIN, int H, int OH, int PADLOW, int OYT, int XT, int CK>
__global__ void __launch_bounds__(8*OYT*XT)
conv_s2_kernel(const float* __restrict__ in, const float* __restrict__ wp,
               const float* __restrict__ bias, float* __restrict__ out)
{
    constexpr int W = H, OW = OH;
    constexpr int PX   = OYT*XT;          // quads per cout-group
    constexpr int NT   = 8*PX;
    constexpr int RP   = 2*OYT + 1;
    constexpr int EP   = 4*XT + 4;        // plane pitch, mult of 4
    constexpr int ROWF = 2*EP + 4;        // row pitch: NOT a multiple of 32
    constexpr int SRAW = 8*XT + 1;        // raw columns staged
    constexpr int IN_SZ = CK*RP*ROWF;
    constexpr int W_SZ  = CK*64*12;       // floats

    __shared__ __align__(16) float s_in[IN_SZ];
    __shared__ __align__(16) float s_w[W_SZ];

    const int n   = blockIdx.x;
    const int oy0 = blockIdx.y * OYT;
    const int tid = threadIdx.x;
    const int cy  = tid / PX;             // cout group 0..7 -> couts cy*8..cy*8+7
    const int px  = tid % PX;
    const int oyl = px / XT;
    const int x0  = (px % XT) * 4;

    float acc[8][4];
#pragma unroll
    for (int i = 0; i < 8; i++)
#pragma unroll
        for (int j = 0; j < 4; j++) acc[i][j] = 0.f;

    for (int c0 = 0; c0 < CIN; c0 += CK) {
        // ---- stage input tile, de-interleaved even/odd columns ----
        for (int idx = tid; idx < CK*RP*SRAW; idx += NT) {
            int c   = idx / (RP*SRAW);
            int rem = idx - c*(RP*SRAW);
            int r   = rem / SRAW;
            int s   = rem - r*SRAW;
            int gr  = 2*oy0 + r - PADLOW;
            int gc  = s - PADLOW;
            float v = 0.f;
            if (gr >= 0 && gr < H && gc >= 0 && gc < W)
                v = in[((n*CIN + c0 + c)*H + gr)*W + gc];
            s_in[(c*RP + r)*ROWF + (s & 1)*EP + (s >> 1)] = v;
        }
        // ---- stage prepacked weights: straight float4 copy ----
        {
            const float4* src = (const float4*)(wp + c0*(64*12));
            float4* dst = (float4*)s_w;
            for (int idx = tid; idx < W_SZ/4; idx += NT)
                dst[idx] = src[idx];
        }
        __syncthreads();

#pragma unroll
        for (int c = 0; c < CK; c++) {
            const float* base = &s_in[(c*RP + 2*oyl)*ROWF + x0];
#pragma unroll
            for (int ky = 0; ky < 3; ky++) {
                const float* rp = base + ky*ROWF;
                float4 E = *(const float4*)rp;        // even[x0..x0+3]
                float  e4 = rp[4];                     // even[x0+4]
                float4 O = *(const float4*)(rp + EP);  // odd [x0..x0+3]
                const float Ev[5] = {E.x, E.y, E.z, E.w, e4};
                const float Ov[4] = {O.x, O.y, O.z, O.w};
#pragma unroll
                for (int co = 0; co < 8; co++) {
                    float4 wv = *(const float4*)&s_w[((c*64 + cy*8 + co)*3 + ky)*4];
#pragma unroll
                    for (int p = 0; p < 4; p++) {
                        float a = acc[co][p];
                        a = fmaf(wv.x, Ev[p],   a);
                        a = fmaf(wv.y, Ov[p],   a);
                        a = fmaf(wv.z, Ev[p+1], a);
                        acc[co][p] = a;
                    }
                }
            }
        }
        __syncthreads();
    }

    // ---- epilogue ----
    const int oy = oy0 + oyl;
    if (oy < OH) {
#pragma unroll
        for (int co = 0; co < 8; co++) {
            const int cout = cy*8 + co;
            const float bb = bias[cout];
            float* op = &out[((n*64 + cout)*OH + oy)*OW];
#pragma unroll
            for (int p = 0; p < 4; p++) {
                int x = x0 + p;
                if (x < OW) {
                    float v = acc[co][p] + bb;
                    op[x] = v > 0.f ? v : 0.f;
                }
            }
        }
    }
}

// ---------------- prototypes + inverse norms ----------------
__global__ void protos_kernel(const float* __restrict__ emb, const int* __restrict__ y,
                              float* __restrict__ protos, float* __restrict__ protoInv)
{
    const int b = blockIdx.x / 5, c = blockIdx.x % 5;
    const int tid = threadIdx.x;                   // 256
    __shared__ int sels[25];
    if (tid < 25) sels[tid] = ((y[b*25 + tid] % 5) == c) ? 1 : 0;
    __syncthreads();

    float sq = 0.f;
    for (int d = tid; d < 2304; d += 256) {
        float v = 0.f;
#pragma unroll
        for (int s = 0; s < 25; s++)
            if (sels[s]) v += emb[(b*25 + s)*2304 + d];
        v = v / 5.0f;                              // CAP = 5
        protos[(b*5 + c)*2304 + d] = v;
        sq += v*v;
    }
    __shared__ float red[256];
    red[tid] = sq; __syncthreads();
    for (int s = 128; s > 0; s >>= 1) {
        if (tid < s) red[tid] += red[tid + s];
        __syncthreads();
    }
    if (tid == 0) protoInv[b*5 + c] = 1.f / fmaxf(sqrtf(red[0]), 1e-8f);
}

// ---------------- cosine logits ----------------
__global__ void preds_kernel(const float* __restrict__ emb, const float* __restrict__ protos,
                             const float* __restrict__ protoInv, float* __restrict__ out)
{
    const int b = blockIdx.x / 75, t = blockIdx.x % 75;
    const int tid = threadIdx.x;                   // 256
    float dot[5] = {0,0,0,0,0};
    float nsq = 0.f;
    const float* e = emb + (size_t)(200 + b*75 + t)*2304;
    for (int d = tid; d < 2304; d += 256) {
        float ev = e[d];
        nsq += ev*ev;
#pragma unroll
        for (int c = 0; c < 5; c++)
            dot[c] = fmaf(ev, protos[(b*5 + c)*2304 + d], dot[c]);
    }
    __shared__ float red[256];
    __shared__ float res[6];
    for (int q = 0; q < 6; q++) {
        red[tid] = (q == 0) ? nsq : dot[q-1];
        __syncthreads();
        for (int s = 128; s > 0; s >>= 1) {
            if (tid < s) red[tid] += red[tid + s];
            __syncthreads();
        }
        if (tid == 0) res[q] = red[0];
        __syncthreads();
    }
    if (tid < 5) {
        float inv_t = 1.f / fmaxf(sqrtf(res[0]), 1e-8f);
        out[(b*75 + t)*5 + tid] = res[1 + tid] * inv_t * protoInv[b*5 + tid];
    }
}

// ---------------- launch ----------------
extern "C" void kernel_launch(void* const* d_in, const int* in_sizes, int n_in,
                              void* d_out, int out_size)
{
    const float* xs = (const float*)d_in[0];
    const float* xt = (const float*)d_in[1];
    const int*   y  = (const int*)  d_in[2];
    const float* W1 = (const float*)d_in[3];
    const float* b1 = (const float*)d_in[4];
    const float* W2 = (const float*)d_in[5];
    const float* b2 = (const float*)d_in[6];
    const float* W3 = (const float*)d_in[7];
    const float* b3 = (const float*)d_in[8];
    const float* W4 = (const float*)d_in[9];
    const float* b4 = (const float*)d_in[10];
    float* out = (float*)d_out;

    float *bufA, *bufB, *bufC, *bufD, *pr, *pi;
    float *wp1, *wp2, *wp3, *wp4;
    cudaGetSymbolAddress((void**)&bufA, g_bufA);
    cudaGetSymbolAddress((void**)&bufB, g_bufB);
    cudaGetSymbolAddress((void**)&bufC, g_bufC);
    cudaGetSymbolAddress((void**)&bufD, g_bufD);
    cudaGetSymbolAddress((void**)&pr,   g_protos);
    cudaGetSymbolAddress((void**)&pi,   g_protoInv);
    cudaGetSymbolAddress((void**)&wp1,  g_wp1);
    cudaGetSymbolAddress((void**)&wp2,  g_wp2);
    cudaGetSymbolAddress((void**)&wp3,  g_wp3);
    cudaGetSymbolAddress((void**)&wp4,  g_wp4);

    // prepack weights (tiny)
    prepack_kernel<<<(3*64*12 + 255)/256, 256>>>(W1, wp1, 3);
    prepack_kernel<<<(64*64*12 + 255)/256, 256>>>(W2, wp2, 64);
    prepack_kernel<<<(64*64*12 + 255)/256, 256>>>(W3, wp3, 64);
    prepack_kernel<<<(64*64*12 + 255)/256, 256>>>(W4, wp4, 64);

    // <CIN,H,OH,PADLOW, OYT,XT,CK>
    // conv1: 3->64, 84->42. OYT=4, XT=11 (44 cols), NT=352, grid(.,11)
    conv_s2_kernel<3,84,42,0, 4,11,3><<<dim3(200,11), 352>>>(xs, wp1, b1, bufA);
    conv_s2_kernel<3,84,42,0, 4,11,3><<<dim3(600,11), 352>>>(xt, wp1, b1, bufA + (size_t)200*64*42*42);
    // conv2: 64->64, 42->21. OYT=7, XT=6 (24 cols), NT=336, grid(800,3)
    conv_s2_kernel<64,42,21,0, 7,6,8><<<dim3(800,3), 336>>>(bufA, wp2, b2, bufB);
    // conv3: 64->64, 21->11, pad_low=1. OYT=11 (whole), XT=3, NT=264, grid(800,1)
    conv_s2_kernel<64,21,11,1, 11,3,8><<<dim3(800,1), 264>>>(bufB, wp3, b3, bufC);
    // conv4: 64->64, 11->6, pad_low=1. OYT=6 (whole), XT=2, NT=96, grid(800,1)
    conv_s2_kernel<64,11,6,1, 6,2,8><<<dim3(800,1), 96>>>(bufC, wp4, b4, bufD);
    // head
    protos_kernel<<<40, 256>>>(bufD, y, pr, pi);
    preds_kernel<<<600, 256>>>(bufD, pr, pi, out);
}